// round 6
// baseline (speedup 1.0000x reference)
#include <cuda_runtime.h>
#include <cuda_bf16.h>
#include <cstdint>

#define MAXN 100000
#define MAXE 1600000

// ---------------- scratch ----------------
__device__ float g_ft[MAXN * 64];
__device__ float g_res[MAXN * 64];
__device__ float g_sd[MAXN];
__device__ float g_ss[MAXN];
__device__ int   g_start[MAXN + 1];
__device__ float g_wl[64];
__device__ float g_wr[64];
// B fragments in mma.sync m16n8k16 register layout: [s(8)][j(16)][lane(32)] -> uint2 {b0,b1}
__device__ __align__(16) uint2 g_Bfh[8 * 16 * 32];
__device__ __align__(16) uint2 g_Bfl[8 * 16 * 32];

union BU { __nv_bfloat162 h; uint32_t u; };

// ---------------- mma.sync helpers (sm_80-era path, works on sm_100 base target) ----------------
__device__ __forceinline__ void mma16816(float* c, const uint32_t* a, uint32_t b0, uint32_t b1) {
    asm volatile(
        "mma.sync.aligned.m16n8k16.row.col.f32.bf16.bf16.f32 "
        "{%0,%1,%2,%3}, {%4,%5,%6,%7}, {%8,%9}, {%0,%1,%2,%3};"
        : "+f"(c[0]), "+f"(c[1]), "+f"(c[2]), "+f"(c[3])
        : "r"(a[0]), "r"(a[1]), "r"(a[2]), "r"(a[3]), "r"(b0), "r"(b1));
}
__device__ __forceinline__ void ldsm4(uint32_t* r, uint32_t addr) {
    asm volatile("ldmatrix.sync.aligned.m8n8.x4.shared.b16 {%0,%1,%2,%3}, [%4];"
        : "=r"(r[0]), "=r"(r[1]), "=r"(r[2]), "=r"(r[3]) : "r"(addr));
}
__device__ __forceinline__ uint32_t smem_u32(const void* p) {
    uint32_t a;
    asm("{ .reg .u64 t; cvta.to.shared.u64 t, %1; cvt.u32.u64 %0, t; }" : "=r"(a) : "l"(p));
    return a;
}

// ---------------- prep: W row-sums + B fragments (hi/lo bf16 split) ----------------
__global__ void k_prep(const float* __restrict__ Wfc, const float* __restrict__ Wl,
                       const float* __restrict__ Wr, const float* __restrict__ Wres) {
    int idx = blockIdx.x * 256 + threadIdx.x;     // 0..4095
    int lane = idx & 31, j = (idx >> 5) & 15, s = idx >> 9;
    int n = j * 8 + (lane >> 2);
    int kb = s * 16 + (lane & 3) * 2;
    const float* W = (n < 64) ? Wfc : Wres;
    int nn = (n < 64) ? n : n - 64;
    float v0 = W[(kb + 0) * 64 + nn], v1 = W[(kb + 1) * 64 + nn];
    float v2 = W[(kb + 8) * 64 + nn], v3 = W[(kb + 9) * 64 + nn];
    __nv_bfloat16 h0 = __float2bfloat16(v0), h1 = __float2bfloat16(v1);
    __nv_bfloat16 h2 = __float2bfloat16(v2), h3 = __float2bfloat16(v3);
    BU b0h, b1h, b0l, b1l;
    b0h.h = __nv_bfloat162(h0, h1);
    b1h.h = __nv_bfloat162(h2, h3);
    b0l.h = __floats2bfloat162_rn(v0 - __bfloat162float(h0), v1 - __bfloat162float(h1));
    b1l.h = __floats2bfloat162_rn(v2 - __bfloat162float(h2), v3 - __bfloat162float(h3));
    g_Bfh[idx] = make_uint2(b0h.u, b1h.u);
    g_Bfl[idx] = make_uint2(b0l.u, b1l.u);
    if (idx < 64) {
        float a = 0.f, b = 0.f;
#pragma unroll
        for (int t = 0; t < 64; t++) { a += Wl[idx * 64 + t]; b += Wr[idx * 64 + t]; }
        g_wl[idx] = a;
        g_wr[idx] = b;
    }
}

// ---------------- mma GEMM: [128 nodes x 128 cols] per block; cols 0..63=ft, 64..127=res ----------------
#define APITCH 136
#define SM_A_HI 0
#define SM_A_LO 34816
#define SM_BFH  69632
#define SM_BFL  102400
#define SM_WL   135168
#define SM_WR   135424
#define SM_SSD  135680
#define SM_SSS  136192
#define SM_TOT  136704

__global__ void __launch_bounds__(256) k_gemm_mma(const float* __restrict__ feats, int N) {
    extern __shared__ char smem[];
    uint32_t sb = smem_u32(smem);
    int tid = threadIdx.x, wid = tid >> 5, lane = tid & 31;
    int wm = wid & 1, wn = wid >> 1;
    int nb = blockIdx.x * 128;

    {
        const uint4* srch = (const uint4*)g_Bfh;
        const uint4* srcl = (const uint4*)g_Bfl;
        uint4* dsth = (uint4*)(smem + SM_BFH);
        uint4* dstl = (uint4*)(smem + SM_BFL);
#pragma unroll
        for (int i = 0; i < 8; i++) {
            dsth[tid + 256 * i] = srch[tid + 256 * i];
            dstl[tid + 256 * i] = srcl[tid + 256 * i];
        }
        if (tid < 64) {
            ((float*)(smem + SM_WL))[tid] = g_wl[tid];
            ((float*)(smem + SM_WR))[tid] = g_wr[tid];
        }
        if (tid < 128) {
            ((float*)(smem + SM_SSD))[tid] = 0.f;
            ((float*)(smem + SM_SSS))[tid] = 0.f;
        }
    }
    {
        int row = tid >> 1, kh = (tid & 1) * 64;
        int n = nb + row;
        const float4* frow = (const float4*)(feats + (size_t)n * 128 + kh);
        char* dh = smem + SM_A_HI + row * (APITCH * 2) + kh * 2;
        char* dl = smem + SM_A_LO + row * (APITCH * 2) + kh * 2;
#pragma unroll
        for (int i = 0; i < 8; i++) {
            float4 f0, f1;
            if (n < N) { f0 = frow[2 * i]; f1 = frow[2 * i + 1]; }
            else { f0 = make_float4(0, 0, 0, 0); f1 = f0; }
            BU h0, h1, h2, h3, l0, l1, l2, l3;
            h0.h = __floats2bfloat162_rn(f0.x, f0.y);
            h1.h = __floats2bfloat162_rn(f0.z, f0.w);
            h2.h = __floats2bfloat162_rn(f1.x, f1.y);
            h3.h = __floats2bfloat162_rn(f1.z, f1.w);
            l0.h = __floats2bfloat162_rn(f0.x - __low2float(h0.h), f0.y - __high2float(h0.h));
            l1.h = __floats2bfloat162_rn(f0.z - __low2float(h1.h), f0.w - __high2float(h1.h));
            l2.h = __floats2bfloat162_rn(f1.x - __low2float(h2.h), f1.y - __high2float(h2.h));
            l3.h = __floats2bfloat162_rn(f1.z - __low2float(h3.h), f1.w - __high2float(h3.h));
            *(uint4*)(dh + 16 * i) = make_uint4(h0.u, h1.u, h2.u, h3.u);
            *(uint4*)(dl + 16 * i) = make_uint4(l0.u, l1.u, l2.u, l3.u);
        }
    }
    __syncthreads();

    float acc[4][4][4];
#pragma unroll
    for (int a = 0; a < 4; a++)
#pragma unroll
        for (int b = 0; b < 4; b++)
#pragma unroll
            for (int c = 0; c < 4; c++) acc[a][b][c] = 0.f;

    uint32_t aRow = (uint32_t)(wm * 64 + ((lane >> 3) & 1) * 8 + (lane & 7));
    uint32_t aK   = (uint32_t)(((lane >> 4) & 1) * 8);
    uint32_t aHi0 = sb + SM_A_HI + aRow * (APITCH * 2) + aK * 2;
    const uint2* sBh = (const uint2*)(smem + SM_BFH);
    const uint2* sBl = (const uint2*)(smem + SM_BFL);

#pragma unroll
    for (int s = 0; s < 8; s++) {
        uint32_t ah[4][4], al[4][4];
#pragma unroll
        for (int mi = 0; mi < 4; mi++) {
            uint32_t ad = aHi0 + mi * (16 * APITCH * 2) + s * 32;
            ldsm4(ah[mi], ad);
            ldsm4(al[mi], ad + (SM_A_LO - SM_A_HI));
        }
#pragma unroll
        for (int ji = 0; ji < 4; ji++) {
            int bi = (s * 16 + wn * 4 + ji) * 32 + lane;
            uint2 bh = sBh[bi];
            uint2 bl = sBl[bi];
#pragma unroll
            for (int mi = 0; mi < 4; mi++) {
                mma16816(acc[mi][ji], ah[mi], bh.x, bh.y);
                mma16816(acc[mi][ji], ah[mi], bl.x, bl.y);
                mma16816(acc[mi][ji], al[mi], bh.x, bh.y);
            }
        }
    }

    {
        float* dst = (wn < 2) ? g_ft : g_res;
        int cbase = wn * 32 + (lane & 3) * 2 - ((wn < 2) ? 0 : 64);
        int rbase = wm * 64 + (lane >> 2);
        const float* swl = (const float*)(smem + SM_WL);
        const float* swr = (const float*)(smem + SM_WR);
        float* ssd = (float*)(smem + SM_SSD);
        float* sss = (float*)(smem + SM_SSS);

#pragma unroll
        for (int mi = 0; mi < 4; mi++) {
            int r0 = rbase + mi * 16;
            int n0 = nb + r0, n1 = n0 + 8;
#pragma unroll
            for (int ji = 0; ji < 4; ji++) {
                int c = cbase + ji * 8;
                if (n0 < N) *(float2*)(dst + (size_t)n0 * 64 + c) = make_float2(acc[mi][ji][0], acc[mi][ji][1]);
                if (n1 < N) *(float2*)(dst + (size_t)n1 * 64 + c) = make_float2(acc[mi][ji][2], acc[mi][ji][3]);
            }
            if (wn < 2) {
#pragma unroll
                for (int q = 0; q < 2; q++) {
                    float pd = 0.f, ps = 0.f;
#pragma unroll
                    for (int ji = 0; ji < 4; ji++) {
                        int c = cbase + ji * 8;
                        float x0 = acc[mi][ji][q * 2], x1 = acc[mi][ji][q * 2 + 1];
                        pd += x0 * swl[c] + x1 * swl[c + 1];
                        ps += x0 * swr[c] + x1 * swr[c + 1];
                    }
                    pd += __shfl_xor_sync(0xffffffffu, pd, 1);
                    pd += __shfl_xor_sync(0xffffffffu, pd, 2);
                    ps += __shfl_xor_sync(0xffffffffu, ps, 1);
                    ps += __shfl_xor_sync(0xffffffffu, ps, 2);
                    if ((lane & 3) == 0) {
                        atomicAdd(&ssd[r0 + q * 8], pd);
                        atomicAdd(&sss[r0 + q * 8], ps);
                    }
                }
            }
        }
    }
    __syncthreads();
    if (tid < 128) {
        int n = nb + tid;
        if (n < N) {
            g_sd[n] = ((float*)(smem + SM_SSD))[tid];
            g_ss[n] = ((float*)(smem + SM_SSS))[tid];
        }
    }
}

// ---------------- CSR offsets from sorted edge_dst ----------------
__global__ void k_csr(const int* __restrict__ dst, int E, int N) {
    int e = blockIdx.x * blockDim.x + threadIdx.x;
    if (e < E) {
        int d = dst[e];
        int dp = (e == 0) ? -1 : dst[e - 1];
        for (int n = dp + 1; n <= d; n++) g_start[n] = e;
    } else if (e == E) {
        int dl = dst[E - 1];
        for (int n = dl + 1; n <= N; n++) g_start[n] = E;
    }
}

// ---------------- one warp per dst node; 8-lane-per-edge gather, packed (w,off) ----------------
__global__ void __launch_bounds__(256) k_agg(const int* __restrict__ src,
                                             float* __restrict__ out, int N) {
    __shared__ float2 stg[8][132];
    int wid = threadIdx.x >> 5, lane = threadIdx.x & 31;
    int gw = blockIdx.x * 8 + wid;
    if (gw >= N) return;

    int beg = g_start[gw], end = g_start[gw + 1], deg = end - beg;
    float sdn = g_sd[gw];
    const float NEG = -3.402823e38f;

    if (deg <= 128) {
        // ---- score phase: up to 4 edges/lane in registers; store (w, byte-offset) ----
        int e = beg + lane;
        int s0 = 0, s1 = 0, s2 = 0, s3 = 0;
        float c0 = NEG, c1 = NEG, c2 = NEG, c3 = NEG;
        if (e < end)      { s0 = src[e];      float t = sdn + g_ss[s0]; c0 = t > 0.f ? t : 0.01f * t; }
        if (e + 32 < end) { s1 = src[e + 32]; float t = sdn + g_ss[s1]; c1 = t > 0.f ? t : 0.01f * t; }
        if (e + 64 < end) { s2 = src[e + 64]; float t = sdn + g_ss[s2]; c2 = t > 0.f ? t : 0.01f * t; }
        if (e + 96 < end) { s3 = src[e + 96]; float t = sdn + g_ss[s3]; c3 = t > 0.f ? t : 0.01f * t; }
        float mx = fmaxf(fmaxf(c0, c1), fmaxf(c2, c3));
#pragma unroll
        for (int o = 16; o; o >>= 1) mx = fmaxf(mx, __shfl_xor_sync(0xffffffffu, mx, o));
        float w0 = __expf(c0 - mx), w1 = __expf(c1 - mx), w2 = __expf(c2 - mx), w3 = __expf(c3 - mx);
        float sum = w0 + w1 + w2 + w3;
#pragma unroll
        for (int o = 16; o; o >>= 1) sum += __shfl_xor_sync(0xffffffffu, sum, o);
        float inv = 1.0f / sum;
        if (e < end)      stg[wid][lane]      = make_float2(w0 * inv, __uint_as_float((uint32_t)s0 * 256u));
        if (e + 32 < end) stg[wid][lane + 32] = make_float2(w1 * inv, __uint_as_float((uint32_t)s1 * 256u));
        if (e + 64 < end) stg[wid][lane + 64] = make_float2(w2 * inv, __uint_as_float((uint32_t)s2 * 256u));
        if (e + 96 < end) stg[wid][lane + 96] = make_float2(w3 * inv, __uint_as_float((uint32_t)s3 * 256u));
        int degp = (deg + 3) & ~3;  // pad to multiple of 4 with zero weight
        if (lane < 3 && deg + lane < degp) stg[wid][deg + lane] = make_float2(0.f, __uint_as_float(0u));
        __syncwarp();

        // ---- gather phase: 8 lanes per edge (4 edges per warp-iteration), 32 B per lane ----
        int grp = lane >> 3, l8 = lane & 7;
        const char* pbase = (const char*)g_ft + l8 * 32;
        const float2* st = stg[wid];
        float4 a0 = make_float4(0.f, 0.f, 0.f, 0.f);
        float4 a1 = make_float4(0.f, 0.f, 0.f, 0.f);
        for (int i = grp; i < degp; i += 4) {
            float2 p = st[i];
            float w = p.x;
            uint32_t o = __float_as_uint(p.y);
            const float4 f0 = *(const float4*)(pbase + o);
            const float4 f1 = *(const float4*)(pbase + o + 16);
            a0.x = fmaf(w, f0.x, a0.x);
            a0.y = fmaf(w, f0.y, a0.y);
            a0.z = fmaf(w, f0.z, a0.z);
            a0.w = fmaf(w, f0.w, a0.w);
            a1.x = fmaf(w, f1.x, a1.x);
            a1.y = fmaf(w, f1.y, a1.y);
            a1.z = fmaf(w, f1.z, a1.z);
            a1.w = fmaf(w, f1.w, a1.w);
        }
        // fold 4 edge-groups
#pragma unroll
        for (int o = 8; o <= 16; o <<= 1) {
            a0.x += __shfl_xor_sync(0xffffffffu, a0.x, o);
            a0.y += __shfl_xor_sync(0xffffffffu, a0.y, o);
            a0.z += __shfl_xor_sync(0xffffffffu, a0.z, o);
            a0.w += __shfl_xor_sync(0xffffffffu, a0.w, o);
            a1.x += __shfl_xor_sync(0xffffffffu, a1.x, o);
            a1.y += __shfl_xor_sync(0xffffffffu, a1.y, o);
            a1.z += __shfl_xor_sync(0xffffffffu, a1.z, o);
            a1.w += __shfl_xor_sync(0xffffffffu, a1.w, o);
        }
        if (grp == 0) {
            const char* rbase = (const char*)g_res + (size_t)gw * 256 + l8 * 32;
            const float4 r0 = *(const float4*)rbase;
            const float4 r1 = *(const float4*)(rbase + 16);
            float4 v0 = make_float4(r0.x + a0.x, r0.y + a0.y, r0.z + a0.z, r0.w + a0.w);
            float4 v1 = make_float4(r1.x + a1.x, r1.y + a1.y, r1.z + a1.z, r1.w + a1.w);
            v0.x = v0.x > 0.f ? v0.x : expm1f(v0.x);
            v0.y = v0.y > 0.f ? v0.y : expm1f(v0.y);
            v0.z = v0.z > 0.f ? v0.z : expm1f(v0.z);
            v0.w = v0.w > 0.f ? v0.w : expm1f(v0.w);
            v1.x = v1.x > 0.f ? v1.x : expm1f(v1.x);
            v1.y = v1.y > 0.f ? v1.y : expm1f(v1.y);
            v1.z = v1.z > 0.f ? v1.z : expm1f(v1.z);
            v1.w = v1.w > 0.f ? v1.w : expm1f(v1.w);
            char* obase = (char*)out + (size_t)gw * 256 + l8 * 32;
            *(float4*)obase = v0;
            *(float4*)(obase + 16) = v1;
        }
    } else {
        // streaming fallback (rare)
        float mx = NEG;
        for (int e = beg + lane; e < end; e += 32) {
            float t = sdn + g_ss[src[e]];
            t = t > 0.f ? t : 0.01f * t;
            mx = fmaxf(mx, t);
        }
#pragma unroll
        for (int o = 16; o; o >>= 1) mx = fmaxf(mx, __shfl_xor_sync(0xffffffffu, mx, o));
        float sum = 0.f;
        for (int e = beg + lane; e < end; e += 32) {
            float t = sdn + g_ss[src[e]];
            t = t > 0.f ? t : 0.01f * t;
            sum += __expf(t - mx);
        }
#pragma unroll
        for (int o = 16; o; o >>= 1) sum += __shfl_xor_sync(0xffffffffu, sum, o);
        float inv = 1.0f / sum;
        float accx = 0.f, accy = 0.f;
        for (int base = beg; base < end; base += 32) {
            int e = base + lane;
            int s = 0; float w = 0.f;
            if (e < end) {
                s = src[e];
                float t = sdn + g_ss[s];
                t = t > 0.f ? t : 0.01f * t;
                w = __expf(t - mx) * inv;
            }
            stg[wid][lane] = make_float2(w, __int_as_float(s));
            __syncwarp();
            int cnt = min(32, end - base);
            for (int i = 0; i < cnt; i++) {
                float2 p = stg[wid][i];
                int si = __float_as_int(p.y);
                const float2 f = *(const float2*)(g_ft + (size_t)si * 64 + 2 * lane);
                accx = fmaf(p.x, f.x, accx);
                accy = fmaf(p.x, f.y, accy);
            }
            __syncwarp();
        }
        const float2 r2 = *(const float2*)(g_res + (size_t)gw * 64 + 2 * lane);
        float vx = r2.x + accx, vy = r2.y + accy;
        vx = vx > 0.f ? vx : expm1f(vx);
        vy = vy > 0.f ? vy : expm1f(vy);
        ((float2*)out)[gw * 32 + lane] = make_float2(vx, vy);
    }
}

// ---------------- launch ----------------
extern "C" void kernel_launch(void* const* d_in, const int* in_sizes, int n_in,
                              void* d_out, int out_size) {
    const float* feats = (const float*)d_in[0];
    const float* Wfc   = (const float*)d_in[1];
    const float* Wl    = (const float*)d_in[2];
    const float* Wr    = (const float*)d_in[3];
    const float* Wres  = (const float*)d_in[4];
    const int*   esrc  = (const int*)d_in[5];
    const int*   edst  = (const int*)d_in[6];

    int N = in_sizes[0] / 128;
    int E = in_sizes[5];

    cudaFuncSetAttribute(k_gemm_mma, cudaFuncAttributeMaxDynamicSharedMemorySize, SM_TOT);

    k_prep<<<16, 256>>>(Wfc, Wl, Wr, Wres);
    k_gemm_mma<<<(N + 127) / 128, 256, SM_TOT>>>(feats, N);
    k_csr<<<(E + 1 + 255) / 256, 256>>>(edst, E, N);
    k_agg<<<(N + 7) / 8, 256>>>(esrc, (float*)d_out, N);
}

// round 7
// speedup vs baseline: 1.1394x; 1.1394x over previous
#include <cuda_runtime.h>
#include <cuda_bf16.h>
#include <cstdint>

#define MAXN 100000
#define MAXE 1600000

// ---------------- scratch ----------------
__device__ float g_ft[MAXN * 64];
__device__ float g_res[MAXN * 64];
__device__ float g_sd[MAXN];
__device__ float g_ss[MAXN];
__device__ int   g_start[MAXN + 1];
__device__ float g_wl[64];
__device__ float g_wr[64];
// B fragments in mma.sync m16n8k16 register layout: [s(8)][j(16)][lane(32)] -> uint2 {b0,b1}
__device__ __align__(16) uint2 g_Bfh[8 * 16 * 32];
__device__ __align__(16) uint2 g_Bfl[8 * 16 * 32];

union BU { __nv_bfloat162 h; uint32_t u; };

// ---------------- mma.sync helpers (sm_80-era path, works on sm_100 base target) ----------------
__device__ __forceinline__ void mma16816(float* c, const uint32_t* a, uint32_t b0, uint32_t b1) {
    asm volatile(
        "mma.sync.aligned.m16n8k16.row.col.f32.bf16.bf16.f32 "
        "{%0,%1,%2,%3}, {%4,%5,%6,%7}, {%8,%9}, {%0,%1,%2,%3};"
        : "+f"(c[0]), "+f"(c[1]), "+f"(c[2]), "+f"(c[3])
        : "r"(a[0]), "r"(a[1]), "r"(a[2]), "r"(a[3]), "r"(b0), "r"(b1));
}
__device__ __forceinline__ void ldsm4(uint32_t* r, uint32_t addr) {
    asm volatile("ldmatrix.sync.aligned.m8n8.x4.shared.b16 {%0,%1,%2,%3}, [%4];"
        : "=r"(r[0]), "=r"(r[1]), "=r"(r[2]), "=r"(r[3]) : "r"(addr));
}
__device__ __forceinline__ uint32_t smem_u32(const void* p) {
    uint32_t a;
    asm("{ .reg .u64 t; cvta.to.shared.u64 t, %1; cvt.u32.u64 %0, t; }" : "=r"(a) : "l"(p));
    return a;
}

// ---------------- prep: W row-sums + B fragments (hi/lo bf16 split) ----------------
__global__ void k_prep(const float* __restrict__ Wfc, const float* __restrict__ Wl,
                       const float* __restrict__ Wr, const float* __restrict__ Wres) {
    int idx = blockIdx.x * 256 + threadIdx.x;     // 0..4095
    int lane = idx & 31, j = (idx >> 5) & 15, s = idx >> 9;
    int n = j * 8 + (lane >> 2);
    int kb = s * 16 + (lane & 3) * 2;
    const float* W = (n < 64) ? Wfc : Wres;
    int nn = (n < 64) ? n : n - 64;
    float v0 = W[(kb + 0) * 64 + nn], v1 = W[(kb + 1) * 64 + nn];
    float v2 = W[(kb + 8) * 64 + nn], v3 = W[(kb + 9) * 64 + nn];
    __nv_bfloat16 h0 = __float2bfloat16(v0), h1 = __float2bfloat16(v1);
    __nv_bfloat16 h2 = __float2bfloat16(v2), h3 = __float2bfloat16(v3);
    BU b0h, b1h, b0l, b1l;
    b0h.h = __nv_bfloat162(h0, h1);
    b1h.h = __nv_bfloat162(h2, h3);
    b0l.h = __floats2bfloat162_rn(v0 - __bfloat162float(h0), v1 - __bfloat162float(h1));
    b1l.h = __floats2bfloat162_rn(v2 - __bfloat162float(h2), v3 - __bfloat162float(h3));
    g_Bfh[idx] = make_uint2(b0h.u, b1h.u);
    g_Bfl[idx] = make_uint2(b0l.u, b1l.u);
    if (idx < 64) {
        float a = 0.f, b = 0.f;
#pragma unroll
        for (int t = 0; t < 64; t++) { a += Wl[idx * 64 + t]; b += Wr[idx * 64 + t]; }
        g_wl[idx] = a;
        g_wr[idx] = b;
    }
}

// ---------------- mma GEMM: [128 nodes x 128 cols] per block; cols 0..63=ft, 64..127=res ----------------
#define APITCH 136
#define SM_A_HI 0
#define SM_A_LO 34816
#define SM_BFH  69632
#define SM_BFL  102400
#define SM_WL   135168
#define SM_WR   135424
#define SM_SSD  135680
#define SM_SSS  136192
#define SM_TOT  136704

__global__ void __launch_bounds__(256) k_gemm_mma(const float* __restrict__ feats, int N) {
    extern __shared__ char smem[];
    uint32_t sb = smem_u32(smem);
    int tid = threadIdx.x, wid = tid >> 5, lane = tid & 31;
    int wm = wid & 1, wn = wid >> 1;
    int nb = blockIdx.x * 128;

    {
        const uint4* srch = (const uint4*)g_Bfh;
        const uint4* srcl = (const uint4*)g_Bfl;
        uint4* dsth = (uint4*)(smem + SM_BFH);
        uint4* dstl = (uint4*)(smem + SM_BFL);
#pragma unroll
        for (int i = 0; i < 8; i++) {
            dsth[tid + 256 * i] = srch[tid + 256 * i];
            dstl[tid + 256 * i] = srcl[tid + 256 * i];
        }
        if (tid < 64) {
            ((float*)(smem + SM_WL))[tid] = g_wl[tid];
            ((float*)(smem + SM_WR))[tid] = g_wr[tid];
        }
        if (tid < 128) {
            ((float*)(smem + SM_SSD))[tid] = 0.f;
            ((float*)(smem + SM_SSS))[tid] = 0.f;
        }
    }
    {
        int row = tid >> 1, kh = (tid & 1) * 64;
        int n = nb + row;
        const float4* frow = (const float4*)(feats + (size_t)n * 128 + kh);
        char* dh = smem + SM_A_HI + row * (APITCH * 2) + kh * 2;
        char* dl = smem + SM_A_LO + row * (APITCH * 2) + kh * 2;
#pragma unroll
        for (int i = 0; i < 8; i++) {
            float4 f0, f1;
            if (n < N) { f0 = frow[2 * i]; f1 = frow[2 * i + 1]; }
            else { f0 = make_float4(0, 0, 0, 0); f1 = f0; }
            BU h0, h1, h2, h3, l0, l1, l2, l3;
            h0.h = __floats2bfloat162_rn(f0.x, f0.y);
            h1.h = __floats2bfloat162_rn(f0.z, f0.w);
            h2.h = __floats2bfloat162_rn(f1.x, f1.y);
            h3.h = __floats2bfloat162_rn(f1.z, f1.w);
            l0.h = __floats2bfloat162_rn(f0.x - __low2float(h0.h), f0.y - __high2float(h0.h));
            l1.h = __floats2bfloat162_rn(f0.z - __low2float(h1.h), f0.w - __high2float(h1.h));
            l2.h = __floats2bfloat162_rn(f1.x - __low2float(h2.h), f1.y - __high2float(h2.h));
            l3.h = __floats2bfloat162_rn(f1.z - __low2float(h3.h), f1.w - __high2float(h3.h));
            *(uint4*)(dh + 16 * i) = make_uint4(h0.u, h1.u, h2.u, h3.u);
            *(uint4*)(dl + 16 * i) = make_uint4(l0.u, l1.u, l2.u, l3.u);
        }
    }
    __syncthreads();

    float acc[4][4][4];
#pragma unroll
    for (int a = 0; a < 4; a++)
#pragma unroll
        for (int b = 0; b < 4; b++)
#pragma unroll
            for (int c = 0; c < 4; c++) acc[a][b][c] = 0.f;

    uint32_t aRow = (uint32_t)(wm * 64 + ((lane >> 3) & 1) * 8 + (lane & 7));
    uint32_t aK   = (uint32_t)(((lane >> 4) & 1) * 8);
    uint32_t aHi0 = sb + SM_A_HI + aRow * (APITCH * 2) + aK * 2;
    const uint2* sBh = (const uint2*)(smem + SM_BFH);
    const uint2* sBl = (const uint2*)(smem + SM_BFL);

#pragma unroll
    for (int s = 0; s < 8; s++) {
        uint32_t ah[4][4], al[4][4];
#pragma unroll
        for (int mi = 0; mi < 4; mi++) {
            uint32_t ad = aHi0 + mi * (16 * APITCH * 2) + s * 32;
            ldsm4(ah[mi], ad);
            ldsm4(al[mi], ad + (SM_A_LO - SM_A_HI));
        }
#pragma unroll
        for (int ji = 0; ji < 4; ji++) {
            int bi = (s * 16 + wn * 4 + ji) * 32 + lane;
            uint2 bh = sBh[bi];
            uint2 bl = sBl[bi];
#pragma unroll
            for (int mi = 0; mi < 4; mi++) {
                mma16816(acc[mi][ji], ah[mi], bh.x, bh.y);
                mma16816(acc[mi][ji], ah[mi], bl.x, bl.y);
                mma16816(acc[mi][ji], al[mi], bh.x, bh.y);
            }
        }
    }

    {
        float* dst = (wn < 2) ? g_ft : g_res;
        int cbase = wn * 32 + (lane & 3) * 2 - ((wn < 2) ? 0 : 64);
        int rbase = wm * 64 + (lane >> 2);
        const float* swl = (const float*)(smem + SM_WL);
        const float* swr = (const float*)(smem + SM_WR);
        float* ssd = (float*)(smem + SM_SSD);
        float* sss = (float*)(smem + SM_SSS);

#pragma unroll
        for (int mi = 0; mi < 4; mi++) {
            int r0 = rbase + mi * 16;
            int n0 = nb + r0, n1 = n0 + 8;
#pragma unroll
            for (int ji = 0; ji < 4; ji++) {
                int c = cbase + ji * 8;
                if (n0 < N) *(float2*)(dst + (size_t)n0 * 64 + c) = make_float2(acc[mi][ji][0], acc[mi][ji][1]);
                if (n1 < N) *(float2*)(dst + (size_t)n1 * 64 + c) = make_float2(acc[mi][ji][2], acc[mi][ji][3]);
            }
            if (wn < 2) {
#pragma unroll
                for (int q = 0; q < 2; q++) {
                    float pd = 0.f, ps = 0.f;
#pragma unroll
                    for (int ji = 0; ji < 4; ji++) {
                        int c = cbase + ji * 8;
                        float x0 = acc[mi][ji][q * 2], x1 = acc[mi][ji][q * 2 + 1];
                        pd += x0 * swl[c] + x1 * swl[c + 1];
                        ps += x0 * swr[c] + x1 * swr[c + 1];
                    }
                    pd += __shfl_xor_sync(0xffffffffu, pd, 1);
                    pd += __shfl_xor_sync(0xffffffffu, pd, 2);
                    ps += __shfl_xor_sync(0xffffffffu, ps, 1);
                    ps += __shfl_xor_sync(0xffffffffu, ps, 2);
                    if ((lane & 3) == 0) {
                        atomicAdd(&ssd[r0 + q * 8], pd);
                        atomicAdd(&sss[r0 + q * 8], ps);
                    }
                }
            }
        }
    }
    __syncthreads();
    if (tid < 128) {
        int n = nb + tid;
        if (n < N) {
            g_sd[n] = ((float*)(smem + SM_SSD))[tid];
            g_ss[n] = ((float*)(smem + SM_SSS))[tid];
        }
    }
}

// ---------------- CSR offsets from sorted edge_dst ----------------
__global__ void k_csr(const int* __restrict__ dst, int E, int N) {
    int e = blockIdx.x * blockDim.x + threadIdx.x;
    if (e < E) {
        int d = dst[e];
        int dp = (e == 0) ? -1 : dst[e - 1];
        for (int n = dp + 1; n <= d; n++) g_start[n] = e;
    } else if (e == E) {
        int dl = dst[E - 1];
        for (int n = dl + 1; n <= N; n++) g_start[n] = E;
    }
}

// ---------------- 2 dst nodes per warp, 16 lanes each; float4 row gather ----------------
__global__ void __launch_bounds__(256) k_agg(const int* __restrict__ src,
                                             float* __restrict__ out, int N) {
    __shared__ float2 stg[8][2][130];
    int wid = threadIdx.x >> 5, lane = threadIdx.x & 31;
    int half = lane >> 4, l16 = lane & 15;
    uint32_t hm = 0xFFFFu << (half * 16);
    int gw = blockIdx.x * 16 + wid * 2 + half;
    if (gw >= N) return;

    int beg = g_start[gw], end = g_start[gw + 1], deg = end - beg;
    float sdn = g_sd[gw];
    const float NEG = -3.402823e38f;
    float2* st = stg[wid][half];

    if (deg <= 128) {
        // ---- score phase: up to 8 edges per lane ----
        int s[8];
        float c[8];
#pragma unroll
        for (int j = 0; j < 8; j++) {
            int e = beg + l16 + j * 16;
            if (e < end) {
                s[j] = src[e];
                float t = sdn + g_ss[s[j]];
                c[j] = t > 0.f ? t : 0.01f * t;
            } else c[j] = NEG;
        }
        float mx = c[0];
#pragma unroll
        for (int j = 1; j < 8; j++) mx = fmaxf(mx, c[j]);
#pragma unroll
        for (int o = 8; o; o >>= 1) mx = fmaxf(mx, __shfl_xor_sync(hm, mx, o));
        float w[8], sum = 0.f;
#pragma unroll
        for (int j = 0; j < 8; j++) { w[j] = __expf(c[j] - mx); sum += w[j]; }
#pragma unroll
        for (int o = 8; o; o >>= 1) sum += __shfl_xor_sync(hm, sum, o);
        float inv = 1.0f / sum;
#pragma unroll
        for (int j = 0; j < 8; j++) {
            int e = beg + l16 + j * 16;
            if (e < end)
                st[l16 + j * 16] = make_float2(w[j] * inv, __uint_as_float((uint32_t)s[j] * 256u));
        }
        __syncwarp();

        // ---- gather: one edge per half-iteration; 16 lanes x float4 = full row ----
        const char* pbase = (const char*)g_ft + l16 * 16;
        float4 acc = make_float4(0.f, 0.f, 0.f, 0.f);
        for (int i = 0; i < deg; i++) {
            float2 p = st[i];
            const float4 f = *(const float4*)(pbase + __float_as_uint(p.y));
            acc.x = fmaf(p.x, f.x, acc.x);
            acc.y = fmaf(p.x, f.y, acc.y);
            acc.z = fmaf(p.x, f.z, acc.z);
            acc.w = fmaf(p.x, f.w, acc.w);
        }

        const float4 r4 = *(const float4*)((const char*)g_res + (size_t)gw * 256 + l16 * 16);
        float vx = r4.x + acc.x, vy = r4.y + acc.y, vz = r4.z + acc.z, vw = r4.w + acc.w;
        vx = vx > 0.f ? vx : expm1f(vx);
        vy = vy > 0.f ? vy : expm1f(vy);
        vz = vz > 0.f ? vz : expm1f(vz);
        vw = vw > 0.f ? vw : expm1f(vw);
        *(float4*)((char*)out + (size_t)gw * 256 + l16 * 16) = make_float4(vx, vy, vz, vw);
    } else {
        // streaming fallback (rare for Poisson(16) degrees)
        float mx = NEG;
        for (int e = beg + l16; e < end; e += 16) {
            float t = sdn + g_ss[src[e]];
            t = t > 0.f ? t : 0.01f * t;
            mx = fmaxf(mx, t);
        }
#pragma unroll
        for (int o = 8; o; o >>= 1) mx = fmaxf(mx, __shfl_xor_sync(hm, mx, o));
        float sum = 0.f;
        for (int e = beg + l16; e < end; e += 16) {
            float t = sdn + g_ss[src[e]];
            t = t > 0.f ? t : 0.01f * t;
            sum += __expf(t - mx);
        }
#pragma unroll
        for (int o = 8; o; o >>= 1) sum += __shfl_xor_sync(hm, sum, o);
        float inv = 1.0f / sum;

        const char* pbase = (const char*)g_ft + l16 * 16;
        float4 acc = make_float4(0.f, 0.f, 0.f, 0.f);
        for (int base = beg; base < end; base += 16) {
            int e = base + l16;
            float wv = 0.f;
            uint32_t off = 0;
            if (e < end) {
                int sv = src[e];
                float t = sdn + g_ss[sv];
                t = t > 0.f ? t : 0.01f * t;
                wv = __expf(t - mx) * inv;
                off = (uint32_t)sv * 256u;
            }
            int cnt = min(16, end - base);
            for (int i = 0; i < cnt; i++) {
                float wi = __shfl_sync(hm, wv, half * 16 + i);
                uint32_t oi = __shfl_sync(hm, off, half * 16 + i);
                const float4 f = *(const float4*)(pbase + oi);
                acc.x = fmaf(wi, f.x, acc.x);
                acc.y = fmaf(wi, f.y, acc.y);
                acc.z = fmaf(wi, f.z, acc.z);
                acc.w = fmaf(wi, f.w, acc.w);
            }
        }
        const float4 r4 = *(const float4*)((const char*)g_res + (size_t)gw * 256 + l16 * 16);
        float vx = r4.x + acc.x, vy = r4.y + acc.y, vz = r4.z + acc.z, vw = r4.w + acc.w;
        vx = vx > 0.f ? vx : expm1f(vx);
        vy = vy > 0.f ? vy : expm1f(vy);
        vz = vz > 0.f ? vz : expm1f(vz);
        vw = vw > 0.f ? vw : expm1f(vw);
        *(float4*)((char*)out + (size_t)gw * 256 + l16 * 16) = make_float4(vx, vy, vz, vw);
    }
}

// ---------------- launch ----------------
extern "C" void kernel_launch(void* const* d_in, const int* in_sizes, int n_in,
                              void* d_out, int out_size) {
    const float* feats = (const float*)d_in[0];
    const float* Wfc   = (const float*)d_in[1];
    const float* Wl    = (const float*)d_in[2];
    const float* Wr    = (const float*)d_in[3];
    const float* Wres  = (const float*)d_in[4];
    const int*   esrc  = (const int*)d_in[5];
    const int*   edst  = (const int*)d_in[6];

    int N = in_sizes[0] / 128;
    int E = in_sizes[5];

    cudaFuncSetAttribute(k_gemm_mma, cudaFuncAttributeMaxDynamicSharedMemorySize, SM_TOT);

    k_prep<<<16, 256>>>(Wfc, Wl, Wr, Wres);
    k_gemm_mma<<<(N + 127) / 128, 256, SM_TOT>>>(feats, N);
    k_csr<<<(E + 1 + 255) / 256, 256>>>(edst, E, N);
    k_agg<<<(N + 15) / 16, 256>>>(esrc, (float*)d_out, N);
}

// round 8
// speedup vs baseline: 1.2775x; 1.1212x over previous
#include <cuda_runtime.h>
#include <cuda_bf16.h>
#include <cstdint>

#define MAXN 100000
#define MAXE 1600000

// ---------------- scratch ----------------
__device__ float g_ft[MAXN * 64];
__device__ float g_res[MAXN * 64];
__device__ float g_sd[MAXN];
__device__ float g_ss[MAXN];
__device__ int   g_start[MAXN + 1];
__device__ float g_wl[64];
__device__ float g_wr[64];
// B fragments in mma.sync m16n8k16 register layout: [s(8)][j(16)][lane(32)] -> uint2 {b0,b1}
__device__ __align__(16) uint2 g_Bfh[8 * 16 * 32];
__device__ __align__(16) uint2 g_Bfl[8 * 16 * 32];

union BU { __nv_bfloat162 h; uint32_t u; };

// ---------------- mma.sync helpers ----------------
__device__ __forceinline__ void mma16816(float* c, const uint32_t* a, uint32_t b0, uint32_t b1) {
    asm volatile(
        "mma.sync.aligned.m16n8k16.row.col.f32.bf16.bf16.f32 "
        "{%0,%1,%2,%3}, {%4,%5,%6,%7}, {%8,%9}, {%0,%1,%2,%3};"
        : "+f"(c[0]), "+f"(c[1]), "+f"(c[2]), "+f"(c[3])
        : "r"(a[0]), "r"(a[1]), "r"(a[2]), "r"(a[3]), "r"(b0), "r"(b1));
}
__device__ __forceinline__ void ldsm4(uint32_t* r, uint32_t addr) {
    asm volatile("ldmatrix.sync.aligned.m8n8.x4.shared.b16 {%0,%1,%2,%3}, [%4];"
        : "=r"(r[0]), "=r"(r[1]), "=r"(r[2]), "=r"(r[3]) : "r"(addr));
}
__device__ __forceinline__ uint32_t smem_u32(const void* p) {
    uint32_t a;
    asm("{ .reg .u64 t; cvta.to.shared.u64 t, %1; cvt.u32.u64 %0, t; }" : "=r"(a) : "l"(p));
    return a;
}

// ---------------- prep: W row-sums + B fragments (hi/lo bf16 split) ----------------
__global__ void k_prep(const float* __restrict__ Wfc, const float* __restrict__ Wl,
                       const float* __restrict__ Wr, const float* __restrict__ Wres) {
    int idx = blockIdx.x * 256 + threadIdx.x;     // 0..4095
    int lane = idx & 31, j = (idx >> 5) & 15, s = idx >> 9;
    int n = j * 8 + (lane >> 2);
    int kb = s * 16 + (lane & 3) * 2;
    const float* W = (n < 64) ? Wfc : Wres;
    int nn = (n < 64) ? n : n - 64;
    float v0 = W[(kb + 0) * 64 + nn], v1 = W[(kb + 1) * 64 + nn];
    float v2 = W[(kb + 8) * 64 + nn], v3 = W[(kb + 9) * 64 + nn];
    __nv_bfloat16 h0 = __float2bfloat16(v0), h1 = __float2bfloat16(v1);
    __nv_bfloat16 h2 = __float2bfloat16(v2), h3 = __float2bfloat16(v3);
    BU b0h, b1h, b0l, b1l;
    b0h.h = __nv_bfloat162(h0, h1);
    b1h.h = __nv_bfloat162(h2, h3);
    b0l.h = __floats2bfloat162_rn(v0 - __bfloat162float(h0), v1 - __bfloat162float(h1));
    b1l.h = __floats2bfloat162_rn(v2 - __bfloat162float(h2), v3 - __bfloat162float(h3));
    g_Bfh[idx] = make_uint2(b0h.u, b1h.u);
    g_Bfl[idx] = make_uint2(b0l.u, b1l.u);
    if (idx < 64) {
        float a = 0.f, b = 0.f;
#pragma unroll
        for (int t = 0; t < 64; t++) { a += Wl[idx * 64 + t]; b += Wr[idx * 64 + t]; }
        g_wl[idx] = a;
        g_wr[idx] = b;
    }
}

// ---------------- mma GEMM: [128 nodes x 128 cols] per block; B frags straight from L1/L2 ----------------
#define APITCH 136
#define SM_A_HI 0
#define SM_A_LO 34816
#define SM_WL   69632
#define SM_WR   69888
#define SM_SSD  70144
#define SM_SSS  70656
#define SM_TOT  71168

__global__ void __launch_bounds__(256, 2) k_gemm_mma(const float* __restrict__ feats, int N) {
    extern __shared__ char smem[];
    uint32_t sb = smem_u32(smem);
    int tid = threadIdx.x, wid = tid >> 5, lane = tid & 31;
    int wm = wid & 1, wn = wid >> 1;
    int nb = blockIdx.x * 128;

    if (tid < 64) {
        ((float*)(smem + SM_WL))[tid] = g_wl[tid];
        ((float*)(smem + SM_WR))[tid] = g_wr[tid];
    }
    if (tid < 128) {
        ((float*)(smem + SM_SSD))[tid] = 0.f;
        ((float*)(smem + SM_SSS))[tid] = 0.f;
    }
    // convert A: fp32 -> bf16 hi/lo into padded smem. thread = (row, k-half)
    {
        int row = tid >> 1, kh = (tid & 1) * 64;
        int n = nb + row;
        const float4* frow = (const float4*)(feats + (size_t)n * 128 + kh);
        char* dh = smem + SM_A_HI + row * (APITCH * 2) + kh * 2;
        char* dl = smem + SM_A_LO + row * (APITCH * 2) + kh * 2;
#pragma unroll
        for (int i = 0; i < 8; i++) {
            float4 f0, f1;
            if (n < N) { f0 = frow[2 * i]; f1 = frow[2 * i + 1]; }
            else { f0 = make_float4(0, 0, 0, 0); f1 = f0; }
            BU h0, h1, h2, h3, l0, l1, l2, l3;
            h0.h = __floats2bfloat162_rn(f0.x, f0.y);
            h1.h = __floats2bfloat162_rn(f0.z, f0.w);
            h2.h = __floats2bfloat162_rn(f1.x, f1.y);
            h3.h = __floats2bfloat162_rn(f1.z, f1.w);
            l0.h = __floats2bfloat162_rn(f0.x - __low2float(h0.h), f0.y - __high2float(h0.h));
            l1.h = __floats2bfloat162_rn(f0.z - __low2float(h1.h), f0.w - __high2float(h1.h));
            l2.h = __floats2bfloat162_rn(f1.x - __low2float(h2.h), f1.y - __high2float(h2.h));
            l3.h = __floats2bfloat162_rn(f1.z - __low2float(h3.h), f1.w - __high2float(h3.h));
            *(uint4*)(dh + 16 * i) = make_uint4(h0.u, h1.u, h2.u, h3.u);
            *(uint4*)(dl + 16 * i) = make_uint4(l0.u, l1.u, l2.u, l3.u);
        }
    }
    __syncthreads();

    float acc[4][4][4];
#pragma unroll
    for (int a = 0; a < 4; a++)
#pragma unroll
        for (int b = 0; b < 4; b++)
#pragma unroll
            for (int c = 0; c < 4; c++) acc[a][b][c] = 0.f;

    uint32_t aRow = (uint32_t)(wm * 64 + ((lane >> 3) & 1) * 8 + (lane & 7));
    uint32_t aK   = (uint32_t)(((lane >> 4) & 1) * 8);
    uint32_t aHi0 = sb + SM_A_HI + aRow * (APITCH * 2) + aK * 2;
    // B fragments direct from global (L1-resident: 64 KB reused by every block)
    const uint2* pBh = g_Bfh + (wn * 4) * 32 + lane;
    const uint2* pBl = g_Bfl + (wn * 4) * 32 + lane;

#pragma unroll
    for (int s = 0; s < 8; s++) {
        uint32_t ah[4][4], al[4][4];
#pragma unroll
        for (int mi = 0; mi < 4; mi++) {
            uint32_t ad = aHi0 + mi * (16 * APITCH * 2) + s * 32;
            ldsm4(ah[mi], ad);
            ldsm4(al[mi], ad + (SM_A_LO - SM_A_HI));
        }
#pragma unroll
        for (int ji = 0; ji < 4; ji++) {
            uint2 bh = pBh[(s * 16 + ji) * 32];
            uint2 bl = pBl[(s * 16 + ji) * 32];
#pragma unroll
            for (int mi = 0; mi < 4; mi++) {
                mma16816(acc[mi][ji], ah[mi], bh.x, bh.y);
                mma16816(acc[mi][ji], ah[mi], bl.x, bl.y);
                mma16816(acc[mi][ji], al[mi], bh.x, bh.y);
            }
        }
    }

    {
        float* dst = (wn < 2) ? g_ft : g_res;
        int cbase = wn * 32 + (lane & 3) * 2 - ((wn < 2) ? 0 : 64);
        int rbase = wm * 64 + (lane >> 2);
        const float* swl = (const float*)(smem + SM_WL);
        const float* swr = (const float*)(smem + SM_WR);
        float* ssd = (float*)(smem + SM_SSD);
        float* sss = (float*)(smem + SM_SSS);

#pragma unroll
        for (int mi = 0; mi < 4; mi++) {
            int r0 = rbase + mi * 16;
            int n0 = nb + r0, n1 = n0 + 8;
#pragma unroll
            for (int ji = 0; ji < 4; ji++) {
                int c = cbase + ji * 8;
                if (n0 < N) *(float2*)(dst + (size_t)n0 * 64 + c) = make_float2(acc[mi][ji][0], acc[mi][ji][1]);
                if (n1 < N) *(float2*)(dst + (size_t)n1 * 64 + c) = make_float2(acc[mi][ji][2], acc[mi][ji][3]);
            }
            if (wn < 2) {
#pragma unroll
                for (int q = 0; q < 2; q++) {
                    float pd = 0.f, ps = 0.f;
#pragma unroll
                    for (int ji = 0; ji < 4; ji++) {
                        int c = cbase + ji * 8;
                        float x0 = acc[mi][ji][q * 2], x1 = acc[mi][ji][q * 2 + 1];
                        pd += x0 * swl[c] + x1 * swl[c + 1];
                        ps += x0 * swr[c] + x1 * swr[c + 1];
                    }
                    pd += __shfl_xor_sync(0xffffffffu, pd, 1);
                    pd += __shfl_xor_sync(0xffffffffu, pd, 2);
                    ps += __shfl_xor_sync(0xffffffffu, ps, 1);
                    ps += __shfl_xor_sync(0xffffffffu, ps, 2);
                    if ((lane & 3) == 0) {
                        atomicAdd(&ssd[r0 + q * 8], pd);
                        atomicAdd(&sss[r0 + q * 8], ps);
                    }
                }
            }
        }
    }
    __syncthreads();
    if (tid < 128) {
        int n = nb + tid;
        if (n < N) {
            g_sd[n] = ((float*)(smem + SM_SSD))[tid];
            g_ss[n] = ((float*)(smem + SM_SSS))[tid];
        }
    }
}

// ---------------- CSR offsets from sorted edge_dst ----------------
__global__ void k_csr(const int* __restrict__ dst, int E, int N) {
    int e = blockIdx.x * blockDim.x + threadIdx.x;
    if (e < E) {
        int d = dst[e];
        int dp = (e == 0) ? -1 : dst[e - 1];
        for (int n = dp + 1; n <= d; n++) g_start[n] = e;
    } else if (e == E) {
        int dl = dst[E - 1];
        for (int n = dl + 1; n <= N; n++) g_start[n] = E;
    }
}

// ---------------- 2 dst nodes per warp, 16 lanes each; 2x-unrolled float4 row gather ----------------
__global__ void __launch_bounds__(256) k_agg(const int* __restrict__ src,
                                             float* __restrict__ out, int N) {
    __shared__ __align__(16) float2 stg[8][2][130];
    int wid = threadIdx.x >> 5, lane = threadIdx.x & 31;
    int half = lane >> 4, l16 = lane & 15;
    uint32_t hm = 0xFFFFu << (half * 16);
    int gw = blockIdx.x * 16 + wid * 2 + half;
    if (gw >= N) return;

    int beg = g_start[gw], end = g_start[gw + 1], deg = end - beg;
    float sdn = g_sd[gw];
    const float NEG = -3.402823e38f;
    float2* st = stg[wid][half];

    if (deg <= 128) {
        // ---- score phase: up to 8 edges per lane ----
        int s[8];
        float c[8];
#pragma unroll
        for (int j = 0; j < 8; j++) {
            int e = beg + l16 + j * 16;
            if (e < end) {
                s[j] = src[e];
                float t = sdn + g_ss[s[j]];
                c[j] = t > 0.f ? t : 0.01f * t;
            } else c[j] = NEG;
        }
        float mx = c[0];
#pragma unroll
        for (int j = 1; j < 8; j++) mx = fmaxf(mx, c[j]);
#pragma unroll
        for (int o = 8; o; o >>= 1) mx = fmaxf(mx, __shfl_xor_sync(hm, mx, o));
        float w[8], sum = 0.f;
#pragma unroll
        for (int j = 0; j < 8; j++) { w[j] = __expf(c[j] - mx); sum += w[j]; }
#pragma unroll
        for (int o = 8; o; o >>= 1) sum += __shfl_xor_sync(hm, sum, o);
        float inv = 1.0f / sum;
#pragma unroll
        for (int j = 0; j < 8; j++) {
            int e = beg + l16 + j * 16;
            if (e < end)
                st[l16 + j * 16] = make_float2(w[j] * inv, __uint_as_float((uint32_t)s[j] * 256u));
        }
        if (l16 == 0 && (deg & 1)) st[deg] = make_float2(0.f, __uint_as_float(0u));  // pad pair
        __syncwarp();

        // ---- gather: 2 edges per iteration, 2 independent LDG.128 chains ----
        const char* pbase = (const char*)g_ft + l16 * 16;
        const float4* stq = (const float4*)st;   // (w0, o0, w1, o1)
        int np = (deg + 1) >> 1;
        float4 a0 = make_float4(0.f, 0.f, 0.f, 0.f);
        float4 a1 = make_float4(0.f, 0.f, 0.f, 0.f);
        for (int i = 0; i < np; i++) {
            float4 pq = stq[i];
            const float4 f0 = *(const float4*)(pbase + __float_as_uint(pq.y));
            const float4 f1 = *(const float4*)(pbase + __float_as_uint(pq.w));
            a0.x = fmaf(pq.x, f0.x, a0.x);
            a0.y = fmaf(pq.x, f0.y, a0.y);
            a0.z = fmaf(pq.x, f0.z, a0.z);
            a0.w = fmaf(pq.x, f0.w, a0.w);
            a1.x = fmaf(pq.z, f1.x, a1.x);
            a1.y = fmaf(pq.z, f1.y, a1.y);
            a1.z = fmaf(pq.z, f1.z, a1.z);
            a1.w = fmaf(pq.z, f1.w, a1.w);
        }
        a0.x += a1.x; a0.y += a1.y; a0.z += a1.z; a0.w += a1.w;

        const float4 r4 = *(const float4*)((const char*)g_res + (size_t)gw * 256 + l16 * 16);
        float vx = r4.x + a0.x, vy = r4.y + a0.y, vz = r4.z + a0.z, vw = r4.w + a0.w;
        vx = vx > 0.f ? vx : expm1f(vx);
        vy = vy > 0.f ? vy : expm1f(vy);
        vz = vz > 0.f ? vz : expm1f(vz);
        vw = vw > 0.f ? vw : expm1f(vw);
        *(float4*)((char*)out + (size_t)gw * 256 + l16 * 16) = make_float4(vx, vy, vz, vw);
    } else {
        // streaming fallback (rare for Poisson(16) degrees)
        float mx = NEG;
        for (int e = beg + l16; e < end; e += 16) {
            float t = sdn + g_ss[src[e]];
            t = t > 0.f ? t : 0.01f * t;
            mx = fmaxf(mx, t);
        }
#pragma unroll
        for (int o = 8; o; o >>= 1) mx = fmaxf(mx, __shfl_xor_sync(hm, mx, o));
        float sum = 0.f;
        for (int e = beg + l16; e < end; e += 16) {
            float t = sdn + g_ss[src[e]];
            t = t > 0.f ? t : 0.01f * t;
            sum += __expf(t - mx);
        }
#pragma unroll
        for (int o = 8; o; o >>= 1) sum += __shfl_xor_sync(hm, sum, o);
        float inv = 1.0f / sum;

        const char* pbase = (const char*)g_ft + l16 * 16;
        float4 acc = make_float4(0.f, 0.f, 0.f, 0.f);
        for (int base = beg; base < end; base += 16) {
            int e = base + l16;
            float wv = 0.f;
            uint32_t off = 0;
            if (e < end) {
                int sv = src[e];
                float t = sdn + g_ss[sv];
                t = t > 0.f ? t : 0.01f * t;
                wv = __expf(t - mx) * inv;
                off = (uint32_t)sv * 256u;
            }
            int cnt = min(16, end - base);
            for (int i = 0; i < cnt; i++) {
                float wi = __shfl_sync(hm, wv, half * 16 + i);
                uint32_t oi = __shfl_sync(hm, off, half * 16 + i);
                const float4 f = *(const float4*)(pbase + oi);
                acc.x = fmaf(wi, f.x, acc.x);
                acc.y = fmaf(wi, f.y, acc.y);
                acc.z = fmaf(wi, f.z, acc.z);
                acc.w = fmaf(wi, f.w, acc.w);
            }
        }
        const float4 r4 = *(const float4*)((const char*)g_res + (size_t)gw * 256 + l16 * 16);
        float vx = r4.x + acc.x, vy = r4.y + acc.y, vz = r4.z + acc.z, vw = r4.w + acc.w;
        vx = vx > 0.f ? vx : expm1f(vx);
        vy = vy > 0.f ? vy : expm1f(vy);
        vz = vz > 0.f ? vz : expm1f(vz);
        vw = vw > 0.f ? vw : expm1f(vw);
        *(float4*)((char*)out + (size_t)gw * 256 + l16 * 16) = make_float4(vx, vy, vz, vw);
    }
}

// ---------------- launch ----------------
extern "C" void kernel_launch(void* const* d_in, const int* in_sizes, int n_in,
                              void* d_out, int out_size) {
    const float* feats = (const float*)d_in[0];
    const float* Wfc   = (const float*)d_in[1];
    const float* Wl    = (const float*)d_in[2];
    const float* Wr    = (const float*)d_in[3];
    const float* Wres  = (const float*)d_in[4];
    const int*   esrc  = (const int*)d_in[5];
    const int*   edst  = (const int*)d_in[6];

    int N = in_sizes[0] / 128;
    int E = in_sizes[5];

    cudaFuncSetAttribute(k_gemm_mma, cudaFuncAttributeMaxDynamicSharedMemorySize, SM_TOT);

    k_prep<<<16, 256>>>(Wfc, Wl, Wr, Wres);
    k_gemm_mma<<<(N + 127) / 128, 256, SM_TOT>>>(feats, N);
    k_csr<<<(E + 1 + 255) / 256, 256>>>(edst, E, N);
    k_agg<<<(N + 15) / 16, 256>>>(esrc, (float*)d_out, N);
}